// round 5
// baseline (speedup 1.0000x reference)
#include <cuda_runtime.h>
#include <cuda_bf16.h>

// result(row) = sum of 11 table lookups.
// 32 bits -> 8 nibbles (chunks). All 528 order<=2 terms are folded into:
//   - 7 Fano-plane trio tables over chunks 0..6 (cover all 21 pairs once)
//   - 3 star trio tables {0,1,7},{2,3,7},{4,5,7} (cover 6 of the (c,7) edges)
//   - 1 pair table {6,7} (edge (6,7) + chunk 7 linear/intra)
// Linear + intra-chunk terms of chunk c (c<7) fold into the Fano trio whose
// first element is c. Trio tables are 16^3 fp32; pair table 16^2.

#define NTAB 11
#define TRIO_FLOATS 4096
#define TOTAL_FLOATS (10 * TRIO_FLOATS + 256)   // 41216 floats = 164864 B

__device__ float g_tab2[TOTAL_FLOATS];

__device__ const int g_chunks[NTAB][3] = {
    {0,1,3},{1,2,4},{2,3,5},{3,4,6},{4,5,0},{5,6,1},{6,0,2},
    {0,1,7},{2,3,7},{4,5,7},{6,7,-1}
};
__device__ const int g_ndim[NTAB]   = {3,3,3,3,3,3,3,3,3,3,2};
__device__ const int g_nedge[NTAB]  = {3,3,3,3,3,3,3,2,2,2,1};
// edges as (local slot a, local slot b)
__device__ const int g_edges[NTAB][3][2] = {
    {{0,1},{0,2},{1,2}}, {{0,1},{0,2},{1,2}}, {{0,1},{0,2},{1,2}},
    {{0,1},{0,2},{1,2}}, {{0,1},{0,2},{1,2}}, {{0,1},{0,2},{1,2}},
    {{0,1},{0,2},{1,2}},
    {{0,2},{1,2},{-1,-1}}, {{0,2},{1,2},{-1,-1}}, {{0,2},{1,2},{-1,-1}},
    {{0,1},{-1,-1},{-1,-1}}
};
// local slot whose chunk's linear+intra terms fold into this table (-1 none)
__device__ const int g_fold[NTAB] = {0,0,0,0,0,0,0,-1,-1,-1,1};
__device__ const int g_toff[NTAB] = {0,4096,8192,12288,16384,20480,24576,
                                     28672,32768,36864,40960};
__device__ const int g_tsize[NTAB] = {4096,4096,4096,4096,4096,4096,4096,
                                      4096,4096,4096,256};

// variables index for global bit pair (i,j), i<j (itertools.combinations order)
__device__ __forceinline__ int pair_v(int i, int j) {
    return 32 + i * 31 - (i * (i - 1)) / 2 + (j - i - 1);
}

__device__ __forceinline__ int nib_of(int4 v) {
    return v.x + 2 * v.y + 4 * v.z + 8 * v.w;
}

__global__ __launch_bounds__(1024) void KOBE_76948634075865_precompute(
    const float* __restrict__ vars) {
    __shared__ float vs[528];
    for (int i = threadIdx.x; i < 528; i += blockDim.x) vs[i] = vars[i];
    __syncthreads();

    int t = blockIdx.x;
    int ndim  = g_ndim[t];
    int nedge = g_nedge[t];
    int size  = g_tsize[t];
    int toff  = g_toff[t];
    int c0 = g_chunks[t][0], c1 = g_chunks[t][1], c2 = g_chunks[t][2];
    int chk[3] = {c0, c1, c2};
    int foldslot = g_fold[t];

    for (int e = threadIdx.x; e < size; e += blockDim.x) {
        // decode local nibble values (slot 0 = highest digit)
        int nloc[3];
        float sl[3][4];
        for (int k = 0; k < ndim; k++) {
            nloc[k] = (e >> (4 * (ndim - 1 - k))) & 15;
            for (int b = 0; b < 4; b++)
                sl[k][b] = 1.0f - 2.0f * (float)((nloc[k] >> b) & 1);
        }

        float acc = 0.0f;

        for (int ed = 0; ed < nedge; ed++) {
            int la = g_edges[t][ed][0], lb = g_edges[t][ed][1];
            int ca = chk[la], cb = chk[lb];
            for (int i2 = 0; i2 < 4; i2++) {
                int gi = 4 * ca + i2;
                for (int j2 = 0; j2 < 4; j2++) {
                    int gj = 4 * cb + j2;
                    int lo = gi < gj ? gi : gj;
                    int hi = gi < gj ? gj : gi;
                    acc += vs[pair_v(lo, hi)] * sl[la][i2] * sl[lb][j2];
                }
            }
        }

        if (foldslot >= 0) {
            int c = chk[foldslot];
            for (int i2 = 0; i2 < 4; i2++) {
                acc += vs[4 * c + i2] * sl[foldslot][i2];        // linear
                for (int j2 = i2 + 1; j2 < 4; j2++)
                    acc += vs[pair_v(4 * c + i2, 4 * c + j2)] *
                           sl[foldslot][i2] * sl[foldslot][j2];  // intra
            }
        }

        g_tab2[toff + e] = acc;
    }
}

__global__ __launch_bounds__(1024) void KOBE_76948634075865_eval(
    const int4* __restrict__ bits, float* __restrict__ out, int batch) {
    extern __shared__ float tab[];
    int tid = threadIdx.x;
    int r = blockIdx.x * 1024 + tid;
    bool active = (r < batch);

    // Prefetch this thread's row (one 128B line) BEFORE the table fill so the
    // DRAM stream overlaps the L2 table broadcast.
    int4 x0, x1, x2, x3, x4, x5, x6, x7;
    if (active) {
        const int4* p = bits + (size_t)r * 8;
        x0 = p[0]; x1 = p[1]; x2 = p[2]; x3 = p[3];
        x4 = p[4]; x5 = p[5]; x6 = p[6]; x7 = p[7];
    } else {
        x0 = x1 = x2 = x3 = x4 = x5 = x6 = x7 = make_int4(0, 0, 0, 0);
    }

    // Cooperative table fill: 41216 floats = 10304 float4
    {
        const float4* src = (const float4*)g_tab2;
        float4* dst = (float4*)tab;
#pragma unroll
        for (int i = 0; i < 11; i++) {
            int j = tid + i * 1024;
            if (j < TOTAL_FLOATS / 4) dst[j] = src[j];
        }
    }
    __syncthreads();
    if (!active) return;

    int n0 = nib_of(x0), n1 = nib_of(x1), n2 = nib_of(x2), n3 = nib_of(x3);
    int n4 = nib_of(x4), n5 = nib_of(x5), n6 = nib_of(x6), n7 = nib_of(x7);

    float v0  = tab[        n0 * 256 + n1 * 16 + n3];
    float v1  = tab[ 4096 + n1 * 256 + n2 * 16 + n4];
    float v2  = tab[ 8192 + n2 * 256 + n3 * 16 + n5];
    float v3  = tab[12288 + n3 * 256 + n4 * 16 + n6];
    float v4  = tab[16384 + n4 * 256 + n5 * 16 + n0];
    float v5  = tab[20480 + n5 * 256 + n6 * 16 + n1];
    float v6  = tab[24576 + n6 * 256 + n0 * 16 + n2];
    float v7  = tab[28672 + n0 * 256 + n1 * 16 + n7];
    float v8  = tab[32768 + n2 * 256 + n3 * 16 + n7];
    float v9  = tab[36864 + n4 * 256 + n5 * 16 + n7];
    float v10 = tab[40960 + n6 * 16  + n7];

    float s0 = (v0 + v1) + (v2 + v3);
    float s1 = (v4 + v5) + (v6 + v7);
    float s2 = (v8 + v9) + v10;
    out[r] = (s0 + s1) + s2;
}

extern "C" void kernel_launch(void* const* d_in, const int* in_sizes, int n_in,
                              void* d_out, int out_size) {
    const int4* bits = (const int4*)d_in[0];    // [BATCH, 32] int32
    const float* vars = (const float*)d_in[1];  // [528] float32
    int batch = in_sizes[0] / 32;
    float* out = (float*)d_out;

    size_t smem = TOTAL_FLOATS * sizeof(float);
    cudaFuncSetAttribute(KOBE_76948634075865_eval,
                         cudaFuncAttributeMaxDynamicSharedMemorySize, (int)smem);

    KOBE_76948634075865_precompute<<<NTAB, 1024>>>(vars);

    int blocks = (batch + 1023) / 1024;
    KOBE_76948634075865_eval<<<blocks, 1024, smem>>>(bits, out, batch);
}

// round 8
// speedup vs baseline: 3.1254x; 3.1254x over previous
#include <cuda_runtime.h>
#include <cuda_bf16.h>

// result(row) = sum over 28 chunk-pair tables T_(A,B)[nib_A][nib_B],
// 32 bits -> 8 nibbles. All 528 order<=2 terms folded into the tables.
// Eval uses lane-transposed coalesced loads + shuffle nibble packing.

#define NPAIRS 28
#define TABSZ (NPAIRS * 256)   // 7168 floats = 28 KB

__device__ float g_tab[TABSZ];

// variables index for pair (i,j), i<j (itertools.combinations order)
__device__ __forceinline__ int pair_v(int i, int j) {
    return 32 + i * 31 - (i * (i - 1)) / 2 + (j - i - 1);
}

__global__ void KOBE_76948634075865_precompute(const float* __restrict__ vars) {
    int p = blockIdx.x;          // chunk-pair index 0..27
    int t = threadIdx.x;         // entry index 0..255
    int a = t >> 4;              // nibble value of chunk A
    int b = t & 15;              // nibble value of chunk B

    // decode p -> (A,B), A<B over 8 chunks
    int A = 0, rem = p, cnt = 7;
    while (rem >= cnt) { rem -= cnt; cnt--; A++; }
    int B = A + 1 + rem;

    float sa[4], sb[4];
#pragma unroll
    for (int k = 0; k < 4; k++) {
        sa[k] = 1.0f - 2.0f * (float)((a >> k) & 1);
        sb[k] = 1.0f - 2.0f * (float)((b >> k) & 1);
    }

    float acc = 0.0f;

    // cross-chunk pair terms (i in chunk A, j in chunk B)
#pragma unroll
    for (int i2 = 0; i2 < 4; i2++) {
        int i = 4 * A + i2;
#pragma unroll
        for (int j2 = 0; j2 < 4; j2++) {
            int j = 4 * B + j2;
            acc += vars[pair_v(i, j)] * sa[i2] * sb[j2];
        }
    }

    // fold intra-chunk + linear terms of chunk A into T_(A,7)
    if (B == 7) {
#pragma unroll
        for (int i2 = 0; i2 < 4; i2++) {
            int i = 4 * A + i2;
            acc += vars[i] * sa[i2];                       // linear
#pragma unroll
            for (int j2 = i2 + 1; j2 < 4; j2++) {
                int j = 4 * A + j2;
                acc += vars[pair_v(i, j)] * sa[i2] * sa[j2];  // intra pair
            }
        }
        // chunk 7's own intra + linear terms go into T_(6,7), b-dependent
        if (A == 6) {
#pragma unroll
            for (int i2 = 0; i2 < 4; i2++) {
                int i = 28 + i2;
                acc += vars[i] * sb[i2];
#pragma unroll
                for (int j2 = i2 + 1; j2 < 4; j2++) {
                    int j = 28 + j2;
                    acc += vars[pair_v(i, j)] * sb[i2] * sb[j2];
                }
            }
        }
    }

    g_tab[p * 256 + a * 16 + b] = acc;
}

__global__ __launch_bounds__(1024) void KOBE_76948634075865_eval(
    const int4* __restrict__ bits, float* __restrict__ out, int batch) {
    __shared__ float tab[TABSZ];
    int tid = threadIdx.x;
    int warp = tid >> 5, lane = tid & 31;
    int grp = lane >> 3;           // 8-lane group (0..3) within warp
    int c = lane & 7;              // this lane's chunk slot

    // Cooperative table fill (28 KB = 1792 float4)
    {
        const float4* src = (const float4*)g_tab;
        float4* dst = (float4*)tab;
        for (int j = tid; j < TABSZ / 4; j += 1024) dst[j] = src[j];
    }

    int base = blockIdx.x * 1024 + warp * 32;   // first row of this warp
    const int4* p = bits + (size_t)base * 8;

    // Lane-transposed load: iteration i reads 32 consecutive int4 (512 B
    // contiguous per warp instruction). Lane computes its chunk's nibble,
    // butterfly-OR packs all 8 nibbles of its group's row, and keeps the
    // packed word for the row it owns (row base + 4*i + grp at i == c).
    unsigned packed = 0;
#pragma unroll
    for (int i = 0; i < 8; i++) {
        int lin = i * 32 + lane;                 // int4 index within warp tile
        int4 x = make_int4(0, 0, 0, 0);
        if (base + (lin >> 3) < batch) x = p[lin];
        int nib = x.x + 2 * x.y + 4 * x.z + 8 * x.w;
        unsigned v = (unsigned)nib << (4 * c);
        v |= __shfl_xor_sync(0xffffffffu, v, 1);
        v |= __shfl_xor_sync(0xffffffffu, v, 2);
        v |= __shfl_xor_sync(0xffffffffu, v, 4);
        if (i == c) packed = v;                  // own row = base + 4*c + grp
    }
    __syncthreads();

    int myrow = base + 4 * c + grp;
    if (myrow >= batch) return;

    int n[8];
#pragma unroll
    for (int k = 0; k < 8; k++) n[k] = (packed >> (4 * k)) & 15;

    float acc0 = 0.f, acc1 = 0.f, acc2 = 0.f, acc3 = 0.f;
    int idx = 0;
#pragma unroll
    for (int A = 0; A < 8; A++) {
#pragma unroll
        for (int B = A + 1; B < 8; B++) {
            float v = tab[idx * 256 + n[A] * 16 + n[B]];
            if ((idx & 3) == 0)      acc0 += v;
            else if ((idx & 3) == 1) acc1 += v;
            else if ((idx & 3) == 2) acc2 += v;
            else                     acc3 += v;
            idx++;
        }
    }
    out[myrow] = (acc0 + acc1) + (acc2 + acc3);
}

extern "C" void kernel_launch(void* const* d_in, const int* in_sizes, int n_in,
                              void* d_out, int out_size) {
    const int4* bits = (const int4*)d_in[0];    // [BATCH, 32] int32
    const float* vars = (const float*)d_in[1];  // [528] float32
    int batch = in_sizes[0] / 32;
    float* out = (float*)d_out;

    KOBE_76948634075865_precompute<<<NPAIRS, 256>>>(vars);

    int blocks = (batch + 1023) / 1024;
    KOBE_76948634075865_eval<<<blocks, 1024>>>(bits, out, batch);
}